// round 11
// baseline (speedup 1.0000x reference)
#include <cuda_runtime.h>
#include <cuda_bf16.h>
#include <math.h>
#include <stdint.h>

// Problem constants
#define BB   2
#define TT   2048
#define NE   1024
#define HH   16
#define DD   64
#define BT   (BB*TT)        // 4096
#define N3   (3*NE)         // 3072
#define BH   (BB*HH)        // 32
#define OSZ  ((size_t)BB*TT*NE)      // 4,194,304
#define ASZ  ((size_t)BB*HH*TT*TT)   // 134,217,728
#define NJT  (TT/128)       // 16 j-tiles

// Scratch (device globals only; no allocation allowed)
__device__ float g_attn_fb[ASZ];
__device__ float g_psum[(size_t)BH*TT*NJT];

// bf16 hi/lo operands
__device__ __align__(16) __nv_bfloat16 g_xh[BT*NE];
__device__ __align__(16) __nv_bfloat16 g_xl[BT*NE];
__device__ __align__(16) __nv_bfloat16 g_wqh[N3*NE];
__device__ __align__(16) __nv_bfloat16 g_wql[N3*NE];
__device__ __align__(16) __nv_bfloat16 g_woh[NE*NE];
__device__ __align__(16) __nv_bfloat16 g_wol[NE*NE];
__device__ __align__(16) __nv_bfloat16 g_avh[BT*NE];
__device__ __align__(16) __nv_bfloat16 g_avl[BT*NE];
__device__ __align__(16) __nv_bfloat16 g_qh[BH*TT*DD];
__device__ __align__(16) __nv_bfloat16 g_ql[BH*TT*DD];
__device__ __align__(16) __nv_bfloat16 g_kh[BH*TT*DD];
__device__ __align__(16) __nv_bfloat16 g_kl[BH*TT*DD];
__device__ __align__(16) __nv_bfloat16 g_vh[BH*TT*DD];
__device__ __align__(16) __nv_bfloat16 g_vl[BH*TT*DD];

// ===========================================================================
// Helpers
// ===========================================================================
__device__ __forceinline__ void hilo4(float4 v, uint2& h, uint2& l) {
    __nv_bfloat16 h0 = __float2bfloat16(v.x);
    __nv_bfloat16 h1 = __float2bfloat16(v.y);
    __nv_bfloat16 h2 = __float2bfloat16(v.z);
    __nv_bfloat16 h3 = __float2bfloat16(v.w);
    __nv_bfloat16 l0 = __float2bfloat16(v.x - __bfloat162float(h0));
    __nv_bfloat16 l1 = __float2bfloat16(v.y - __bfloat162float(h1));
    __nv_bfloat16 l2 = __float2bfloat16(v.z - __bfloat162float(h2));
    __nv_bfloat16 l3 = __float2bfloat16(v.w - __bfloat162float(h3));
    h.x = (uint32_t)__bfloat16_as_ushort(h0) | ((uint32_t)__bfloat16_as_ushort(h1) << 16);
    h.y = (uint32_t)__bfloat16_as_ushort(h2) | ((uint32_t)__bfloat16_as_ushort(h3) << 16);
    l.x = (uint32_t)__bfloat16_as_ushort(l0) | ((uint32_t)__bfloat16_as_ushort(l1) << 16);
    l.y = (uint32_t)__bfloat16_as_ushort(l2) | ((uint32_t)__bfloat16_as_ushort(l3) << 16);
}

__device__ __forceinline__ void pack_hl(float a, float b, uint32_t& ph, uint32_t& pl) {
    __nv_bfloat16 ha = __float2bfloat16(a), hb = __float2bfloat16(b);
    __nv_bfloat16 la = __float2bfloat16(a - __bfloat162float(ha));
    __nv_bfloat16 lb = __float2bfloat16(b - __bfloat162float(hb));
    ph = (uint32_t)__bfloat16_as_ushort(ha) | ((uint32_t)__bfloat16_as_ushort(hb) << 16);
    pl = (uint32_t)__bfloat16_as_ushort(la) | ((uint32_t)__bfloat16_as_ushort(lb) << 16);
}

__device__ __forceinline__ float fexp_s(float s) {
    float y = s * 0.180336880f;            // 0.125 * log2(e)
    y = fminf(fmaxf(y, -60.f), 60.f);
    int   e = __float2int_rn(y);
    float f = y - (float)e;
    float p = 1.54035304e-4f;
    p = fmaf(p, f, 1.33335581e-3f);
    p = fmaf(p, f, 9.61812911e-3f);
    p = fmaf(p, f, 5.55041087e-2f);
    p = fmaf(p, f, 2.40226507e-1f);
    p = fmaf(p, f, 6.93147181e-1f);
    p = fmaf(p, f, 1.0f);
    return p * __int_as_float((e + 127) << 23);
}

__device__ __forceinline__ void mma_bf16(float* c, const uint32_t* a, const uint32_t* b) {
    asm volatile("mma.sync.aligned.m16n8k16.row.col.f32.bf16.bf16.f32 "
        "{%0,%1,%2,%3}, {%4,%5,%6,%7}, {%8,%9}, {%0,%1,%2,%3};"
        : "+f"(c[0]), "+f"(c[1]), "+f"(c[2]), "+f"(c[3])
        : "r"(a[0]), "r"(a[1]), "r"(a[2]), "r"(a[3]), "r"(b[0]), "r"(b[1]));
}

__device__ __forceinline__ void ldsm4(uint32_t& r0, uint32_t& r1, uint32_t& r2, uint32_t& r3,
                                      const void* p) {
    uint32_t a = (uint32_t)__cvta_generic_to_shared(p);
    asm volatile("ldmatrix.sync.aligned.m8n8.x4.shared.b16 {%0,%1,%2,%3}, [%4];"
        : "=r"(r0), "=r"(r1), "=r"(r2), "=r"(r3) : "r"(a));
}

__device__ __forceinline__ void cp16(void* sdst, const void* gsrc) {
    uint32_t sa = (uint32_t)__cvta_generic_to_shared(sdst);
    asm volatile("cp.async.cg.shared.global [%0], [%1], 16;" :: "r"(sa), "l"(gsrc));
}
#define CP_COMMIT() asm volatile("cp.async.commit_group;" ::: "memory")
#define CP_WAIT(n)  asm volatile("cp.async.wait_group %0;" :: "n"(n) : "memory")

// ===========================================================================
// Conversion kernels
// ===========================================================================
__global__ __launch_bounds__(256)
void cvt_kernel(const float* __restrict__ in, __nv_bfloat16* __restrict__ hi,
                __nv_bfloat16* __restrict__ lo, int n4) {
    int i = blockIdx.x * 256 + threadIdx.x;
    if (i >= n4) return;
    float4 v = ((const float4*)in)[i];
    uint2 h, l;
    hilo4(v, h, l);
    ((uint2*)hi)[i] = h;
    ((uint2*)lo)[i] = l;
}

__global__ __launch_bounds__(256)
void cvt_t_kernel(const float* __restrict__ in, __nv_bfloat16* __restrict__ hi,
                  __nv_bfloat16* __restrict__ lo, int K, int N) {
    __shared__ float tile[32][33];
    const int n0 = blockIdx.x * 32, k0 = blockIdx.y * 32;
    const int tx = threadIdx.x, ty = threadIdx.y;
#pragma unroll
    for (int i = 0; i < 32; i += 8)
        tile[ty + i][tx] = in[(size_t)(k0 + ty + i) * N + n0 + tx];
    __syncthreads();
#pragma unroll
    for (int i = 0; i < 32; i += 8) {
        float v = tile[tx][ty + i];
        __nv_bfloat16 h = __float2bfloat16(v);
        size_t oi = (size_t)(n0 + ty + i) * K + k0 + tx;
        hi[oi] = h;
        lo[oi] = __float2bfloat16(v - __bfloat162float(h));
    }
}

// ===========================================================================
// Dense GEMM via mma.sync, hi/lo x3, cp.async double-buffered, ldmatrix.
// Block 128x128, BK=32, 4 warps (128 threads), warp tile 64x64.
// MODE 0 -> q/k/v bf16 hi/lo; MODE 1 -> fp32 row-major.
// ===========================================================================
#define BMT 128
#define BNT 128
#define BKT 32
#define PK  40
#define TILE_E (BMT * PK)
#define STG_B  (4 * TILE_E * 2)
#define GEMM_SMEM (2 * STG_B)             // 81920

template<int MODE>
__global__ __launch_bounds__(128)
void gemm_mma(const __nv_bfloat16* __restrict__ Ah, const __nv_bfloat16* __restrict__ Al,
              const __nv_bfloat16* __restrict__ Bth, const __nv_bfloat16* __restrict__ Btl,
              const float* __restrict__ bias, float* __restrict__ out, int Ktot) {
    extern __shared__ __align__(16) char dsm[];

    const int tid  = threadIdx.x;
    const int warp = tid >> 5, lane = tid & 31;
    const int wm = warp >> 1, wn = warp & 1;         // 2x2 warps, 64x64 tiles
    const int grp = lane >> 2, tig = lane & 3;
    const int m0 = blockIdx.y * BMT, n0 = blockIdx.x * BNT;

    // ldmatrix lane mapping
    const int lm  = lane >> 3;            // matrix index 0..3
    const int lr  = lane & 7;             // row within matrix
    // A: row = (lm&1)*8 + lr, kcol = (lm>>1)*8
    const int a_roff = (lm & 1) * 8 + lr;
    const int a_koff = (lm >> 1) * 8;
    // B: n = (lm>>1)*8 + lr, kcol = (lm&1)*8
    const int b_noff = (lm >> 1) * 8 + lr;
    const int b_koff = (lm & 1) * 8;

    // cp.async per-thread coords: one row per thread, 4 chunks of 16B
    const int lrow = tid;                 // 0..127

    auto issue = [&](int k0, int stage) {
        __nv_bfloat16* b = (__nv_bfloat16*)(dsm + stage * STG_B);
        __nv_bfloat16* pAh = b;
        __nv_bfloat16* pAl = b + TILE_E;
        __nv_bfloat16* pBh = b + 2 * TILE_E;
        __nv_bfloat16* pBl = b + 3 * TILE_E;
#pragma unroll
        for (int ch = 0; ch < 32; ch += 8) {
            cp16(&pAh[lrow * PK + ch], &Ah[(size_t)(m0 + lrow) * Ktot + k0 + ch]);
            cp16(&pAl[lrow * PK + ch], &Al[(size_t)(m0 + lrow) * Ktot + k0 + ch]);
            cp16(&pBh[lrow * PK + ch], &Bth[(size_t)(n0 + lrow) * Ktot + k0 + ch]);
            cp16(&pBl[lrow * PK + ch], &Btl[(size_t)(n0 + lrow) * Ktot + k0 + ch]);
        }
        CP_COMMIT();
    };

    float acc[4][8][4];
#pragma unroll
    for (int a = 0; a < 4; a++)
#pragma unroll
        for (int b = 0; b < 8; b++)
#pragma unroll
            for (int c = 0; c < 4; c++) acc[a][b][c] = 0.f;

    const int NIT = Ktot / BKT;
    issue(0, 0);

    for (int it = 0; it < NIT; ++it) {
        if (it + 1 < NIT) {
            issue((it + 1) * BKT, (it + 1) & 1);
            CP_WAIT(1);
        } else {
            CP_WAIT(0);
        }
        __syncthreads();

        __nv_bfloat16* bp = (__nv_bfloat16*)(dsm + (it & 1) * STG_B);
        const __nv_bfloat16* sAh = bp;
        const __nv_bfloat16* sAl = bp + TILE_E;
        const __nv_bfloat16* sBh = bp + 2 * TILE_E;
        const __nv_bfloat16* sBl = bp + 3 * TILE_E;

#pragma unroll
        for (int kk = 0; kk < BKT; kk += 16) {
            // A fragments: 4 m-tiles, hi + lo (8 LDSM.x4)
            uint32_t ah[4][4], al[4][4];
#pragma unroll
            for (int mt = 0; mt < 4; mt++) {
                int row = wm * 64 + mt * 16 + a_roff;
                ldsm4(ah[mt][0], ah[mt][1], ah[mt][2], ah[mt][3],
                      &sAh[row * PK + kk + a_koff]);
                ldsm4(al[mt][0], al[mt][1], al[mt][2], al[mt][3],
                      &sAl[row * PK + kk + a_koff]);
            }
            // B in two halves of 4 n-tiles to cap live registers
#pragma unroll
            for (int half = 0; half < 2; half++) {
                uint32_t bh[4][2], bl[4][2];
#pragma unroll
                for (int p = 0; p < 2; p++) {
                    int ncol = wn * 64 + half * 32 + p * 16 + b_noff;
                    ldsm4(bh[2*p][0], bh[2*p][1], bh[2*p+1][0], bh[2*p+1][1],
                          &sBh[ncol * PK + kk + b_koff]);
                    ldsm4(bl[2*p][0], bl[2*p][1], bl[2*p+1][0], bl[2*p+1][1],
                          &sBl[ncol * PK + kk + b_koff]);
                }
#pragma unroll
                for (int mt = 0; mt < 4; mt++) {
#pragma unroll
                    for (int nt = 0; nt < 4; nt++) {
                        float* c = acc[mt][half * 4 + nt];
                        mma_bf16(c, ah[mt], bh[nt]);
                        mma_bf16(c, ah[mt], bl[nt]);
                        mma_bf16(c, al[mt], bh[nt]);
                    }
                }
            }
        }
        __syncthreads();
    }

#pragma unroll
    for (int mt = 0; mt < 4; mt++) {
#pragma unroll
        for (int nt = 0; nt < 8; nt++) {
            int r = m0 + wm * 64 + mt * 16 + grp;
            int n = n0 + wn * 64 + nt * 8 + tig * 2;
            float b0 = bias[n], b1 = bias[n + 1];
            float v00 = acc[mt][nt][0] + b0, v01 = acc[mt][nt][1] + b1;
            float v10 = acc[mt][nt][2] + b0, v11 = acc[mt][nt][3] + b1;
            if (MODE == 0) {
                int which = n >> 10;
                int c = n & 1023;
                int h = c >> 6, d = c & 63;
                __nv_bfloat16* dh = (which == 0) ? g_qh : (which == 1) ? g_kh : g_vh;
                __nv_bfloat16* dl = (which == 0) ? g_ql : (which == 1) ? g_kl : g_vl;
                int b = r >> 11, t = r & (TT - 1);
                int bh = b * HH + h;
                size_t base0 = ((size_t)bh * TT + t) * DD + d;
                int t2 = (r + 8) & (TT - 1);
                int bh2 = ((r + 8) >> 11) * HH + h;
                size_t base1 = ((size_t)bh2 * TT + t2) * DD + d;
                uint32_t ph, pl;
                pack_hl(v00, v01, ph, pl);
                *(uint32_t*)&dh[base0] = ph;
                *(uint32_t*)&dl[base0] = pl;
                pack_hl(v10, v11, ph, pl);
                *(uint32_t*)&dh[base1] = ph;
                *(uint32_t*)&dl[base1] = pl;
            } else {
                *(float2*)&out[(size_t)r * NE + n] = make_float2(v00, v01);
                *(float2*)&out[(size_t)(r + 8) * NE + n] = make_float2(v10, v11);
            }
        }
    }
}

// ===========================================================================
// scores_exp: e = exp(QK^T * scale) via MMA hi/lo x3, causal, fused poly-exp.
// ===========================================================================
#define PKA 72
#define SMEM_A_BYTES (4 * 128 * PKA * 2)   // 73728

__global__ __launch_bounds__(256)
void scores_exp(float* __restrict__ attn) {
    const int jt = blockIdx.x, it = blockIdx.y, bh = blockIdx.z;
    const int i0 = it * 128, j0 = jt * 128;
    const int tid = threadIdx.x;
    float* arow = attn + (size_t)bh * TT * TT;

    if (jt > it) {
        float4 z = make_float4(0.f, 0.f, 0.f, 0.f);
#pragma unroll
        for (int i = 0; i < 16; i++) {
            int idx = tid + i * 256;
            int row = idx >> 5;
            int c4  = (idx & 31) << 2;
            *(float4*)&arow[(size_t)(i0 + row) * TT + j0 + c4] = z;
        }
        return;
    }

    extern __shared__ __align__(16) char smem[];
    __nv_bfloat16* sQh = (__nv_bfloat16*)smem;
    __nv_bfloat16* sQl = sQh + 128 * PKA;
    __nv_bfloat16* sKh = sQl + 128 * PKA;
    __nv_bfloat16* sKl = sKh + 128 * PKA;

    const int warp = tid >> 5, lane = tid & 31;
    const int wm = warp >> 2, wn = warp & 3;
    const int grp = lane >> 2, tig = lane & 3;

#pragma unroll
    for (int i = 0; i < 4; i++) {
        int idx = tid + i * 256;
        int row = idx >> 3;
        int ch  = (idx & 7) << 3;
        size_t gq = ((size_t)bh * TT + i0 + row) * DD + ch;
        size_t gk = ((size_t)bh * TT + j0 + row) * DD + ch;
        cp16(&sQh[row * PKA + ch], &g_qh[gq]);
        cp16(&sQl[row * PKA + ch], &g_ql[gq]);
        cp16(&sKh[row * PKA + ch], &g_kh[gk]);
        cp16(&sKl[row * PKA + ch], &g_kl[gk]);
    }
    CP_COMMIT();
    CP_WAIT(0);
    __syncthreads();

    float acc[4][4][4];
#pragma unroll
    for (int a = 0; a < 4; a++)
#pragma unroll
        for (int b = 0; b < 4; b++)
#pragma unroll
            for (int c = 0; c < 4; c++) acc[a][b][c] = 0.f;

#pragma unroll
    for (int kk = 0; kk < 64; kk += 16) {
        int kb = kk + tig * 2;
        uint32_t bhf[4][2], blf[4][2];
#pragma unroll
        for (int nt = 0; nt < 4; nt++) {
            int col = wn * 32 + nt * 8 + grp;
            bhf[nt][0] = *(const uint32_t*)&sKh[col * PKA + kb];
            bhf[nt][1] = *(const uint32_t*)&sKh[col * PKA + kb + 8];
            blf[nt][0] = *(const uint32_t*)&sKl[col * PKA + kb];
            blf[nt][1] = *(const uint32_t*)&sKl[col * PKA + kb + 8];
        }
#pragma unroll
        for (int mt = 0; mt < 4; mt++) {
            int row = wm * 64 + mt * 16 + grp;
            uint32_t ah[4], al[4];
            ah[0] = *(const uint32_t*)&sQh[row * PKA + kb];
            ah[1] = *(const uint32_t*)&sQh[(row + 8) * PKA + kb];
            ah[2] = *(const uint32_t*)&sQh[row * PKA + kb + 8];
            ah[3] = *(const uint32_t*)&sQh[(row + 8) * PKA + kb + 8];
            al[0] = *(const uint32_t*)&sQl[row * PKA + kb];
            al[1] = *(const uint32_t*)&sQl[(row + 8) * PKA + kb];
            al[2] = *(const uint32_t*)&sQl[row * PKA + kb + 8];
            al[3] = *(const uint32_t*)&sQl[(row + 8) * PKA + kb + 8];
#pragma unroll
            for (int nt = 0; nt < 4; nt++) {
                mma_bf16(acc[mt][nt], ah, bhf[nt]);
                mma_bf16(acc[mt][nt], ah, blf[nt]);
                mma_bf16(acc[mt][nt], al, bhf[nt]);
            }
        }
    }
    __syncthreads();

    float* part = (float*)smem;
    float rs0[4], rs1[4];
#pragma unroll
    for (int mt = 0; mt < 4; mt++) { rs0[mt] = 0.f; rs1[mt] = 0.f; }

#pragma unroll
    for (int mt = 0; mt < 4; mt++) {
        int rl = wm * 64 + mt * 16 + grp;
        int gi0 = i0 + rl, gi1 = i0 + rl + 8;
#pragma unroll
        for (int nt = 0; nt < 4; nt++) {
            int nl = wn * 32 + nt * 8 + tig * 2;
            int gj = j0 + nl;
            float e0 = (gj     <= gi0) ? fexp_s(acc[mt][nt][0]) : 0.f;
            float e1 = (gj + 1 <= gi0) ? fexp_s(acc[mt][nt][1]) : 0.f;
            float e2 = (gj     <= gi1) ? fexp_s(acc[mt][nt][2]) : 0.f;
            float e3 = (gj + 1 <= gi1) ? fexp_s(acc[mt][nt][3]) : 0.f;
            *(float2*)&arow[(size_t)gi0 * TT + gj] = make_float2(e0, e1);
            *(float2*)&arow[(size_t)gi1 * TT + gj] = make_float2(e2, e3);
            rs0[mt] += e0 + e1;
            rs1[mt] += e2 + e3;
        }
    }
#pragma unroll
    for (int mt = 0; mt < 4; mt++) {
#pragma unroll
        for (int off = 1; off <= 2; off <<= 1) {
            rs0[mt] += __shfl_xor_sync(0xffffffffu, rs0[mt], off);
            rs1[mt] += __shfl_xor_sync(0xffffffffu, rs1[mt], off);
        }
    }
    if (tig == 0) {
#pragma unroll
        for (int mt = 0; mt < 4; mt++) {
            int rl = wm * 64 + mt * 16 + grp;
            part[wn * 128 + rl]     = rs0[mt];
            part[wn * 128 + rl + 8] = rs1[mt];
        }
    }
    __syncthreads();
    if (tid < 128) {
        float s = part[tid] + part[128 + tid] + part[256 + tid] + part[384 + tid];
        g_psum[((size_t)bh * TT + i0 + tid) * NJT + jt] = s;
    }
}

// ===========================================================================
// pv_fused: normalize (P = e/sum, written back) + P@V via MMA hi/lo x3.
// ===========================================================================
#define SMEM_B_PH   0
#define SMEM_B_PL   (128 * PKA * 2)
#define SMEM_B_VH   (2 * 128 * PKA * 2)
#define SMEM_B_VL   (SMEM_B_VH + 64 * PKA * 2)
#define SMEM_B_INV  (SMEM_B_VL + 64 * PKA * 2)
#define SMEM_B_BYTES (SMEM_B_INV + 128 * 4)

__global__ __launch_bounds__(256)
void pv_fused(float* __restrict__ attn) {
    const int it = blockIdx.x, bh = blockIdx.y;
    const int b = bh >> 4, h = bh & 15;
    const int i0 = it * 128;
    const int tid = threadIdx.x;
    float* arow = attn + (size_t)bh * TT * TT;

    extern __shared__ __align__(16) char smem[];
    __nv_bfloat16* sPh = (__nv_bfloat16*)(smem + SMEM_B_PH);
    __nv_bfloat16* sPl = (__nv_bfloat16*)(smem + SMEM_B_PL);
    __nv_bfloat16* sVh = (__nv_bfloat16*)(smem + SMEM_B_VH);
    __nv_bfloat16* sVl = (__nv_bfloat16*)(smem + SMEM_B_VL);
    float* sInv = (float*)(smem + SMEM_B_INV);

    if (tid < 128) {
        float s = 0.f;
        size_t base = ((size_t)bh * TT + i0 + tid) * NJT;
        for (int q = 0; q <= it; q++) s += g_psum[base + q];
        sInv[tid] = 1.f / s;
    }
    __syncthreads();

    const int warp = tid >> 5, lane = tid & 31;
    const int wm = warp >> 1, wn = warp & 1;
    const int grp = lane >> 2, tig = lane & 3;

    float acc[2][4][4];
#pragma unroll
    for (int a = 0; a < 2; a++)
#pragma unroll
        for (int c = 0; c < 4; c++)
#pragma unroll
            for (int d = 0; d < 4; d++) acc[a][c][d] = 0.f;

    for (int jt = 0; jt <= it; jt++) {
#pragma unroll 1
        for (int jc = 0; jc < 2; jc++) {
            const int j0 = jt * 128 + jc * 64;
#pragma unroll
            for (int i = 0; i < 8; i++) {
                int idx = tid + i * 256;
                int row = idx >> 4;
                int c4  = (idx & 15) << 2;
                float inv = sInv[row];
                float4 v = *(float4*)&arow[(size_t)(i0 + row) * TT + j0 + c4];
                v.x *= inv; v.y *= inv; v.z *= inv; v.w *= inv;
                *(float4*)&arow[(size_t)(i0 + row) * TT + j0 + c4] = v;
                uint2 hp, lp;
                hilo4(v, hp, lp);
                *(uint2*)&sPh[row * PKA + c4] = hp;
                *(uint2*)&sPl[row * PKA + c4] = lp;
            }
#pragma unroll
            for (int i = 0; i < 2; i++) {
                int idx = tid + i * 256;
                int j   = idx >> 3;
                int dch = (idx & 7) << 3;
                size_t gv = ((size_t)bh * TT + j0 + j) * DD + dch;
                uint4 hv = *(const uint4*)&g_vh[gv];
                uint4 lv = *(const uint4*)&g_vl[gv];
                const __nv_bfloat16* hp = (const __nv_bfloat16*)&hv;
                const __nv_bfloat16* lp = (const __nv_bfloat16*)&lv;
#pragma unroll
                for (int e = 0; e < 8; e++) {
                    sVh[(dch + e) * PKA + j] = hp[e];
                    sVl[(dch + e) * PKA + j] = lp[e];
                }
            }
            __syncthreads();
#pragma unroll
            for (int kk = 0; kk < 64; kk += 16) {
                int kb = kk + tig * 2;
                uint32_t bhf[4][2], blf[4][2];
#pragma unroll
                for (int nt = 0; nt < 4; nt++) {
                    int col = wn * 32 + nt * 8 + grp;
                    bhf[nt][0] = *(const uint32_t*)&sVh[col * PKA + kb];
                    bhf[nt][1] = *(const uint32_t*)&sVh[col * PKA + kb + 8];
                    blf[nt][0] = *(const uint32_t*)&sVl[col * PKA + kb];
                    blf[nt][1] = *(const uint32_t*)&sVl[col * PKA + kb + 8];
                }
#pragma unroll
                for (int mt = 0; mt < 2; mt++) {
                    int row = wm * 32 + mt * 16 + grp;
                    uint32_t ah[4], al[4];
                    ah[0] = *(const uint32_t*)&sPh[row * PKA + kb];
                    ah[1] = *(const uint32_t*)&sPh[(row + 8) * PKA + kb];
                    ah[2] = *(const uint32_t*)&sPh[row * PKA + kb + 8];
                    ah[3] = *(const uint32_t*)&sPh[(row + 8) * PKA + kb + 8];
                    al[0] = *(const uint32_t*)&sPl[row * PKA + kb];
                    al[1] = *(const uint32_t*)&sPl[(row + 8) * PKA + kb];
                    al[2] = *(const uint32_t*)&sPl[row * PKA + kb + 8];
                    al[3] = *(const uint32_t*)&sPl[(row + 8) * PKA + kb + 8];
#pragma unroll
                    for (int nt = 0; nt < 4; nt++) {
                        mma_bf16(acc[mt][nt], ah, bhf[nt]);
                        mma_bf16(acc[mt][nt], ah, blf[nt]);
                        mma_bf16(acc[mt][nt], al, bhf[nt]);
                    }
                }
            }
            __syncthreads();
        }
    }

#pragma unroll
    for (int mt = 0; mt < 2; mt++) {
#pragma unroll
        for (int nt = 0; nt < 4; nt++) {
            int t = i0 + wm * 32 + mt * 16 + grp;
            int d = wn * 32 + nt * 8 + tig * 2;
            size_t o0 = ((size_t)b * TT + t) * NE + h * DD + d;
            size_t o1 = ((size_t)b * TT + t + 8) * NE + h * DD + d;
            uint32_t ph, pl;
            pack_hl(acc[mt][nt][0], acc[mt][nt][1], ph, pl);
            *(uint32_t*)&g_avh[o0] = ph;
            *(uint32_t*)&g_avl[o0] = pl;
            pack_hl(acc[mt][nt][2], acc[mt][nt][3], ph, pl);
            *(uint32_t*)&g_avh[o1] = ph;
            *(uint32_t*)&g_avl[o1] = pl;
        }
    }
}

// ---------------------------------------------------------------------------
extern "C" void kernel_launch(void* const* d_in, const int* in_sizes, int n_in,
                              void* d_out, int out_size) {
    const float* x     = (const float*)d_in[0];
    const float* w_qkv = (const float*)d_in[1];
    const float* b_qkv = (const float*)d_in[2];
    const float* w_o   = (const float*)d_in[3];
    const float* b_o   = (const float*)d_in[4];

    float* o_out = (float*)d_out;
    float* attn;
    if ((size_t)out_size >= OSZ + ASZ) {
        attn = (float*)d_out + OSZ;
    } else {
        float* fb = nullptr;
        cudaGetSymbolAddress((void**)&fb, g_attn_fb);
        attn = fb;
    }

    __nv_bfloat16 *xh, *xl, *wqh, *wql, *woh, *wol, *avh, *avl;
    cudaGetSymbolAddress((void**)&xh,  g_xh);
    cudaGetSymbolAddress((void**)&xl,  g_xl);
    cudaGetSymbolAddress((void**)&wqh, g_wqh);
    cudaGetSymbolAddress((void**)&wql, g_wql);
    cudaGetSymbolAddress((void**)&woh, g_woh);
    cudaGetSymbolAddress((void**)&wol, g_wol);
    cudaGetSymbolAddress((void**)&avh, g_avh);
    cudaGetSymbolAddress((void**)&avl, g_avl);

    cudaFuncSetAttribute(gemm_mma<0>, cudaFuncAttributeMaxDynamicSharedMemorySize, GEMM_SMEM);
    cudaFuncSetAttribute(gemm_mma<1>, cudaFuncAttributeMaxDynamicSharedMemorySize, GEMM_SMEM);
    cudaFuncSetAttribute(scores_exp, cudaFuncAttributeMaxDynamicSharedMemorySize, SMEM_A_BYTES);
    cudaFuncSetAttribute(pv_fused,   cudaFuncAttributeMaxDynamicSharedMemorySize, SMEM_B_BYTES);

    // 0) pre-convert operands to bf16 hi/lo
    cvt_kernel<<<(BT * NE / 4 + 255) / 256, 256>>>(x, xh, xl, BT * NE / 4);
    {
        dim3 grid(N3 / 32, NE / 32);
        cvt_t_kernel<<<grid, dim3(32, 8)>>>(w_qkv, wqh, wql, NE, N3);
    }
    {
        dim3 grid(NE / 32, NE / 32);
        cvt_t_kernel<<<grid, dim3(32, 8)>>>(w_o, woh, wol, NE, NE);
    }

    // 1) QKV projection -> q/k/v bf16 hi/lo
    {
        dim3 grid(N3 / BNT, BT / BMT);
        gemm_mma<0><<<grid, 128, GEMM_SMEM>>>(xh, xl, wqh, wql, b_qkv, nullptr, NE);
    }
    // 2) scores + exp + partial row sums
    {
        dim3 grid(NJT, NJT, BH);
        scores_exp<<<grid, 256, SMEM_A_BYTES>>>(attn);
    }
    // 3) normalize (write P) + P@V -> avh/avl
    {
        dim3 grid(NJT, BH);
        pv_fused<<<grid, 256, SMEM_B_BYTES>>>(attn);
    }
    // 4) output projection
    {
        dim3 grid(NE / BNT, BT / BMT);
        gemm_mma<1><<<grid, 128, GEMM_SMEM>>>(avh, avl, woh, wol, b_o, o_out, NE);
    }
}

// round 16
// speedup vs baseline: 1.2593x; 1.2593x over previous
#include <cuda_runtime.h>
#include <cuda_bf16.h>
#include <math.h>
#include <stdint.h>

// Problem constants
#define BB   2
#define TT   2048
#define NE   1024
#define HH   16
#define DD   64
#define BT   (BB*TT)        // 4096
#define N3   (3*NE)         // 3072
#define BH   (BB*HH)        // 32
#define OSZ  ((size_t)BB*TT*NE)      // 4,194,304
#define ASZ  ((size_t)BB*HH*TT*TT)   // 134,217,728
#define NJT  (TT/128)       // 16 j-tiles

// Scratch (device globals only; no allocation allowed)
__device__ float g_attn_fb[ASZ];
__device__ float g_psum[(size_t)BH*TT*NJT];

// bf16 hi/lo operands
__device__ __align__(16) __nv_bfloat16 g_xh[BT*NE];
__device__ __align__(16) __nv_bfloat16 g_xl[BT*NE];
__device__ __align__(16) __nv_bfloat16 g_wqh[N3*NE];
__device__ __align__(16) __nv_bfloat16 g_wql[N3*NE];
__device__ __align__(16) __nv_bfloat16 g_woh[NE*NE];
__device__ __align__(16) __nv_bfloat16 g_wol[NE*NE];
__device__ __align__(16) __nv_bfloat16 g_avh[BT*NE];
__device__ __align__(16) __nv_bfloat16 g_avl[BT*NE];
__device__ __align__(16) __nv_bfloat16 g_qh[BH*TT*DD];
__device__ __align__(16) __nv_bfloat16 g_ql[BH*TT*DD];
__device__ __align__(16) __nv_bfloat16 g_kh[BH*TT*DD];
__device__ __align__(16) __nv_bfloat16 g_kl[BH*TT*DD];
__device__ __align__(16) __nv_bfloat16 g_vh[BH*TT*DD];
__device__ __align__(16) __nv_bfloat16 g_vl[BH*TT*DD];

// ===========================================================================
// Helpers
// ===========================================================================
__device__ __forceinline__ void hilo4(float4 v, uint2& h, uint2& l) {
    __nv_bfloat16 h0 = __float2bfloat16(v.x);
    __nv_bfloat16 h1 = __float2bfloat16(v.y);
    __nv_bfloat16 h2 = __float2bfloat16(v.z);
    __nv_bfloat16 h3 = __float2bfloat16(v.w);
    __nv_bfloat16 l0 = __float2bfloat16(v.x - __bfloat162float(h0));
    __nv_bfloat16 l1 = __float2bfloat16(v.y - __bfloat162float(h1));
    __nv_bfloat16 l2 = __float2bfloat16(v.z - __bfloat162float(h2));
    __nv_bfloat16 l3 = __float2bfloat16(v.w - __bfloat162float(h3));
    h.x = (uint32_t)__bfloat16_as_ushort(h0) | ((uint32_t)__bfloat16_as_ushort(h1) << 16);
    h.y = (uint32_t)__bfloat16_as_ushort(h2) | ((uint32_t)__bfloat16_as_ushort(h3) << 16);
    l.x = (uint32_t)__bfloat16_as_ushort(l0) | ((uint32_t)__bfloat16_as_ushort(l1) << 16);
    l.y = (uint32_t)__bfloat16_as_ushort(l2) | ((uint32_t)__bfloat16_as_ushort(l3) << 16);
}

__device__ __forceinline__ void pack_hl(float a, float b, uint32_t& ph, uint32_t& pl) {
    __nv_bfloat16 ha = __float2bfloat16(a), hb = __float2bfloat16(b);
    __nv_bfloat16 la = __float2bfloat16(a - __bfloat162float(ha));
    __nv_bfloat16 lb = __float2bfloat16(b - __bfloat162float(hb));
    ph = (uint32_t)__bfloat16_as_ushort(ha) | ((uint32_t)__bfloat16_as_ushort(hb) << 16);
    pl = (uint32_t)__bfloat16_as_ushort(la) | ((uint32_t)__bfloat16_as_ushort(lb) << 16);
}

__device__ __forceinline__ float fexp_s(float s) {
    float y = s * 0.180336880f;            // 0.125 * log2(e)
    y = fminf(fmaxf(y, -60.f), 60.f);
    int   e = __float2int_rn(y);
    float f = y - (float)e;
    float p = 1.54035304e-4f;
    p = fmaf(p, f, 1.33335581e-3f);
    p = fmaf(p, f, 9.61812911e-3f);
    p = fmaf(p, f, 5.55041087e-2f);
    p = fmaf(p, f, 2.40226507e-1f);
    p = fmaf(p, f, 6.93147181e-1f);
    p = fmaf(p, f, 1.0f);
    return p * __int_as_float((e + 127) << 23);
}

__device__ __forceinline__ void mma_bf16(float* c, const uint32_t* a, const uint32_t* b) {
    asm volatile("mma.sync.aligned.m16n8k16.row.col.f32.bf16.bf16.f32 "
        "{%0,%1,%2,%3}, {%4,%5,%6,%7}, {%8,%9}, {%0,%1,%2,%3};"
        : "+f"(c[0]), "+f"(c[1]), "+f"(c[2]), "+f"(c[3])
        : "r"(a[0]), "r"(a[1]), "r"(a[2]), "r"(a[3]), "r"(b[0]), "r"(b[1]));
}

__device__ __forceinline__ void ldsm4(uint32_t& r0, uint32_t& r1, uint32_t& r2, uint32_t& r3,
                                      const void* p) {
    uint32_t a = (uint32_t)__cvta_generic_to_shared(p);
    asm volatile("ldmatrix.sync.aligned.m8n8.x4.shared.b16 {%0,%1,%2,%3}, [%4];"
        : "=r"(r0), "=r"(r1), "=r"(r2), "=r"(r3) : "r"(a));
}

__device__ __forceinline__ void cp16(void* sdst, const void* gsrc) {
    uint32_t sa = (uint32_t)__cvta_generic_to_shared(sdst);
    asm volatile("cp.async.cg.shared.global [%0], [%1], 16;" :: "r"(sa), "l"(gsrc));
}
#define CP_COMMIT() asm volatile("cp.async.commit_group;" ::: "memory")
#define CP_WAIT(n)  asm volatile("cp.async.wait_group %0;" :: "n"(n) : "memory")

// ===========================================================================
// Conversion kernels
// ===========================================================================
__global__ __launch_bounds__(256)
void cvt_kernel(const float* __restrict__ in, __nv_bfloat16* __restrict__ hi,
                __nv_bfloat16* __restrict__ lo, int n4) {
    int i = blockIdx.x * 256 + threadIdx.x;
    if (i >= n4) return;
    float4 v = ((const float4*)in)[i];
    uint2 h, l;
    hilo4(v, h, l);
    ((uint2*)hi)[i] = h;
    ((uint2*)lo)[i] = l;
}

__global__ __launch_bounds__(256)
void cvt_t_kernel(const float* __restrict__ in, __nv_bfloat16* __restrict__ hi,
                  __nv_bfloat16* __restrict__ lo, int K, int N) {
    __shared__ float tile[32][33];
    const int n0 = blockIdx.x * 32, k0 = blockIdx.y * 32;
    const int tx = threadIdx.x, ty = threadIdx.y;
#pragma unroll
    for (int i = 0; i < 32; i += 8)
        tile[ty + i][tx] = in[(size_t)(k0 + ty + i) * N + n0 + tx];
    __syncthreads();
#pragma unroll
    for (int i = 0; i < 32; i += 8) {
        float v = tile[tx][ty + i];
        __nv_bfloat16 h = __float2bfloat16(v);
        size_t oi = (size_t)(n0 + ty + i) * K + k0 + tx;
        hi[oi] = h;
        lo[oi] = __float2bfloat16(v - __bfloat162float(h));
    }
}

// ===========================================================================
// Dense GEMM via mma.sync, hi/lo x3, cp.async double-buffered, ldmatrix.
// Block 128x128, BK=32, 8 warps (2x4), warp tile 64x32.  (R6 config + LDSM)
// MODE 0 -> q/k/v bf16 hi/lo; MODE 1 -> fp32 row-major.
// ===========================================================================
#define BMT 128
#define BNT 128
#define BKT 32
#define PK  40
#define TILE_E (BMT * PK)
#define STG_B  (4 * TILE_E * 2)
#define GEMM_SMEM (2 * STG_B)             // 81920

template<int MODE>
__global__ __launch_bounds__(256, 2)
void gemm_mma(const __nv_bfloat16* __restrict__ Ah, const __nv_bfloat16* __restrict__ Al,
              const __nv_bfloat16* __restrict__ Bth, const __nv_bfloat16* __restrict__ Btl,
              const float* __restrict__ bias, float* __restrict__ out, int Ktot) {
    extern __shared__ __align__(16) char dsm[];

    const int tid  = threadIdx.x;
    const int warp = tid >> 5, lane = tid & 31;
    const int wm = warp >> 2, wn = warp & 3;        // 2x4 warps, 64x32 tiles
    const int grp = lane >> 2, tig = lane & 3;
    const int m0 = blockIdx.y * BMT, n0 = blockIdx.x * BNT;

    // ldmatrix lane mapping (validated R11: rel_err bit-identical to scalar loads)
    const int lm  = lane >> 3;
    const int lr  = lane & 7;
    const int a_roff = (lm & 1) * 8 + lr;
    const int a_koff = (lm >> 1) * 8;
    const int b_noff = (lm >> 1) * 8 + lr;
    const int b_koff = (lm & 1) * 8;

    // cp.async per-thread coords: 2 rows per thread, 16B chunk
    const int row0 = tid >> 2;            // 0..63
    const int row1 = row0 + 64;
    const int ch   = (tid & 3) << 3;      // 0,8,16,24

    auto issue = [&](int k0, int stage) {
        __nv_bfloat16* b = (__nv_bfloat16*)(dsm + stage * STG_B);
        __nv_bfloat16* pAh = b;
        __nv_bfloat16* pAl = b + TILE_E;
        __nv_bfloat16* pBh = b + 2 * TILE_E;
        __nv_bfloat16* pBl = b + 3 * TILE_E;
        cp16(&pAh[row0 * PK + ch], &Ah[(size_t)(m0 + row0) * Ktot + k0 + ch]);
        cp16(&pAh[row1 * PK + ch], &Ah[(size_t)(m0 + row1) * Ktot + k0 + ch]);
        cp16(&pAl[row0 * PK + ch], &Al[(size_t)(m0 + row0) * Ktot + k0 + ch]);
        cp16(&pAl[row1 * PK + ch], &Al[(size_t)(m0 + row1) * Ktot + k0 + ch]);
        cp16(&pBh[row0 * PK + ch], &Bth[(size_t)(n0 + row0) * Ktot + k0 + ch]);
        cp16(&pBh[row1 * PK + ch], &Bth[(size_t)(n0 + row1) * Ktot + k0 + ch]);
        cp16(&pBl[row0 * PK + ch], &Btl[(size_t)(n0 + row0) * Ktot + k0 + ch]);
        cp16(&pBl[row1 * PK + ch], &Btl[(size_t)(n0 + row1) * Ktot + k0 + ch]);
        CP_COMMIT();
    };

    float acc[4][4][4];
#pragma unroll
    for (int a = 0; a < 4; a++)
#pragma unroll
        for (int b = 0; b < 4; b++)
#pragma unroll
            for (int c = 0; c < 4; c++) acc[a][b][c] = 0.f;

    const int NIT = Ktot / BKT;
    issue(0, 0);

    for (int it = 0; it < NIT; ++it) {
        if (it + 1 < NIT) {
            issue((it + 1) * BKT, (it + 1) & 1);
            CP_WAIT(1);
        } else {
            CP_WAIT(0);
        }
        __syncthreads();

        __nv_bfloat16* bp = (__nv_bfloat16*)(dsm + (it & 1) * STG_B);
        const __nv_bfloat16* sAh = bp;
        const __nv_bfloat16* sAl = bp + TILE_E;
        const __nv_bfloat16* sBh = bp + 2 * TILE_E;
        const __nv_bfloat16* sBl = bp + 3 * TILE_E;

#pragma unroll
        for (int kk = 0; kk < BKT; kk += 16) {
            // B fragments: 4 n-tiles via 2 LDSM.x4 (hi) + 2 (lo)
            uint32_t bh[4][2], bl[4][2];
#pragma unroll
            for (int p = 0; p < 2; p++) {
                int ncol = wn * 32 + p * 16 + b_noff;
                ldsm4(bh[2*p][0], bh[2*p][1], bh[2*p+1][0], bh[2*p+1][1],
                      &sBh[ncol * PK + kk + b_koff]);
                ldsm4(bl[2*p][0], bl[2*p][1], bl[2*p+1][0], bl[2*p+1][1],
                      &sBl[ncol * PK + kk + b_koff]);
            }
#pragma unroll
            for (int mt = 0; mt < 4; mt++) {
                int row = wm * 64 + mt * 16 + a_roff;
                uint32_t ah[4], al[4];
                ldsm4(ah[0], ah[1], ah[2], ah[3], &sAh[row * PK + kk + a_koff]);
                ldsm4(al[0], al[1], al[2], al[3], &sAl[row * PK + kk + a_koff]);
#pragma unroll
                for (int nt = 0; nt < 4; nt++) {
                    mma_bf16(acc[mt][nt], ah, bh[nt]);
                    mma_bf16(acc[mt][nt], ah, bl[nt]);
                    mma_bf16(acc[mt][nt], al, bh[nt]);
                }
            }
        }
        __syncthreads();
    }

#pragma unroll
    for (int mt = 0; mt < 4; mt++) {
#pragma unroll
        for (int nt = 0; nt < 4; nt++) {
            int r = m0 + wm * 64 + mt * 16 + grp;
            int n = n0 + wn * 32 + nt * 8 + tig * 2;
            float b0 = bias[n], b1 = bias[n + 1];
            float v00 = acc[mt][nt][0] + b0, v01 = acc[mt][nt][1] + b1;
            float v10 = acc[mt][nt][2] + b0, v11 = acc[mt][nt][3] + b1;
            if (MODE == 0) {
                int which = n >> 10;
                int c = n & 1023;
                int h = c >> 6, d = c & 63;
                __nv_bfloat16* dh = (which == 0) ? g_qh : (which == 1) ? g_kh : g_vh;
                __nv_bfloat16* dl = (which == 0) ? g_ql : (which == 1) ? g_kl : g_vl;
                int b = r >> 11, t = r & (TT - 1);
                int bh = b * HH + h;
                size_t base0 = ((size_t)bh * TT + t) * DD + d;
                int t2 = (r + 8) & (TT - 1);
                int bh2 = ((r + 8) >> 11) * HH + h;
                size_t base1 = ((size_t)bh2 * TT + t2) * DD + d;
                uint32_t ph, pl;
                pack_hl(v00, v01, ph, pl);
                *(uint32_t*)&dh[base0] = ph;
                *(uint32_t*)&dl[base0] = pl;
                pack_hl(v10, v11, ph, pl);
                *(uint32_t*)&dh[base1] = ph;
                *(uint32_t*)&dl[base1] = pl;
            } else {
                *(float2*)&out[(size_t)r * NE + n] = make_float2(v00, v01);
                *(float2*)&out[(size_t)(r + 8) * NE + n] = make_float2(v10, v11);
            }
        }
    }
}

// ===========================================================================
// scores_exp: e = exp(QK^T * scale) via MMA hi/lo x3, causal, fused poly-exp.
// 8 warps 2x4, warp tile 64x32, LDSM fragment loads.
// ===========================================================================
#define PKA 72
#define SMEM_A_BYTES (4 * 128 * PKA * 2)   // 73728

__global__ __launch_bounds__(256)
void scores_exp(float* __restrict__ attn) {
    const int jt = blockIdx.x, it = blockIdx.y, bh = blockIdx.z;
    const int i0 = it * 128, j0 = jt * 128;
    const int tid = threadIdx.x;
    float* arow = attn + (size_t)bh * TT * TT;

    if (jt > it) {
        float4 z = make_float4(0.f, 0.f, 0.f, 0.f);
#pragma unroll
        for (int i = 0; i < 16; i++) {
            int idx = tid + i * 256;
            int row = idx >> 5;
            int c4  = (idx & 31) << 2;
            *(float4*)&arow[(size_t)(i0 + row) * TT + j0 + c4] = z;
        }
        return;
    }

    extern __shared__ __align__(16) char smem[];
    __nv_bfloat16* sQh = (__nv_bfloat16*)smem;
    __nv_bfloat16* sQl = sQh + 128 * PKA;
    __nv_bfloat16* sKh = sQl + 128 * PKA;
    __nv_bfloat16* sKl = sKh + 128 * PKA;

    const int warp = tid >> 5, lane = tid & 31;
    const int wm = warp >> 2, wn = warp & 3;
    const int grp = lane >> 2, tig = lane & 3;
    const int lm  = lane >> 3;
    const int lr  = lane & 7;
    const int a_roff = (lm & 1) * 8 + lr;
    const int a_koff = (lm >> 1) * 8;
    const int b_noff = (lm >> 1) * 8 + lr;
    const int b_koff = (lm & 1) * 8;

#pragma unroll
    for (int i = 0; i < 4; i++) {
        int idx = tid + i * 256;
        int row = idx >> 3;
        int ch  = (idx & 7) << 3;
        size_t gq = ((size_t)bh * TT + i0 + row) * DD + ch;
        size_t gk = ((size_t)bh * TT + j0 + row) * DD + ch;
        cp16(&sQh[row * PKA + ch], &g_qh[gq]);
        cp16(&sQl[row * PKA + ch], &g_ql[gq]);
        cp16(&sKh[row * PKA + ch], &g_kh[gk]);
        cp16(&sKl[row * PKA + ch], &g_kl[gk]);
    }
    CP_COMMIT();
    CP_WAIT(0);
    __syncthreads();

    float acc[4][4][4];
#pragma unroll
    for (int a = 0; a < 4; a++)
#pragma unroll
        for (int b = 0; b < 4; b++)
#pragma unroll
            for (int c = 0; c < 4; c++) acc[a][b][c] = 0.f;

#pragma unroll
    for (int kk = 0; kk < 64; kk += 16) {
        uint32_t bhf[4][2], blf[4][2];
#pragma unroll
        for (int p = 0; p < 2; p++) {
            int ncol = wn * 32 + p * 16 + b_noff;
            ldsm4(bhf[2*p][0], bhf[2*p][1], bhf[2*p+1][0], bhf[2*p+1][1],
                  &sKh[ncol * PKA + kk + b_koff]);
            ldsm4(blf[2*p][0], blf[2*p][1], blf[2*p+1][0], blf[2*p+1][1],
                  &sKl[ncol * PKA + kk + b_koff]);
        }
#pragma unroll
        for (int mt = 0; mt < 4; mt++) {
            int row = wm * 64 + mt * 16 + a_roff;
            uint32_t ah[4], al[4];
            ldsm4(ah[0], ah[1], ah[2], ah[3], &sQh[row * PKA + kk + a_koff]);
            ldsm4(al[0], al[1], al[2], al[3], &sQl[row * PKA + kk + a_koff]);
#pragma unroll
            for (int nt = 0; nt < 4; nt++) {
                mma_bf16(acc[mt][nt], ah, bhf[nt]);
                mma_bf16(acc[mt][nt], ah, blf[nt]);
                mma_bf16(acc[mt][nt], al, bhf[nt]);
            }
        }
    }
    __syncthreads();

    float* part = (float*)smem;
    float rs0[4], rs1[4];
#pragma unroll
    for (int mt = 0; mt < 4; mt++) { rs0[mt] = 0.f; rs1[mt] = 0.f; }

#pragma unroll
    for (int mt = 0; mt < 4; mt++) {
        int rl = wm * 64 + mt * 16 + grp;
        int gi0 = i0 + rl, gi1 = i0 + rl + 8;
#pragma unroll
        for (int nt = 0; nt < 4; nt++) {
            int nl = wn * 32 + nt * 8 + tig * 2;
            int gj = j0 + nl;
            float e0 = (gj     <= gi0) ? fexp_s(acc[mt][nt][0]) : 0.f;
            float e1 = (gj + 1 <= gi0) ? fexp_s(acc[mt][nt][1]) : 0.f;
            float e2 = (gj     <= gi1) ? fexp_s(acc[mt][nt][2]) : 0.f;
            float e3 = (gj + 1 <= gi1) ? fexp_s(acc[mt][nt][3]) : 0.f;
            *(float2*)&arow[(size_t)gi0 * TT + gj] = make_float2(e0, e1);
            *(float2*)&arow[(size_t)gi1 * TT + gj] = make_float2(e2, e3);
            rs0[mt] += e0 + e1;
            rs1[mt] += e2 + e3;
        }
    }
#pragma unroll
    for (int mt = 0; mt < 4; mt++) {
#pragma unroll
        for (int off = 1; off <= 2; off <<= 1) {
            rs0[mt] += __shfl_xor_sync(0xffffffffu, rs0[mt], off);
            rs1[mt] += __shfl_xor_sync(0xffffffffu, rs1[mt], off);
        }
    }
    if (tig == 0) {
#pragma unroll
        for (int mt = 0; mt < 4; mt++) {
            int rl = wm * 64 + mt * 16 + grp;
            part[wn * 128 + rl]     = rs0[mt];
            part[wn * 128 + rl + 8] = rs1[mt];
        }
    }
    __syncthreads();
    if (tid < 128) {
        float s = part[tid] + part[128 + tid] + part[256 + tid] + part[384 + tid];
        g_psum[((size_t)bh * TT + i0 + tid) * NJT + jt] = s;
    }
}

// ===========================================================================
// pv_fused: normalize (P = e/sum, written back) + P@V via MMA hi/lo x3.
// 8 warps 4x2, warp tile 32x32, LDSM fragment loads.
// ===========================================================================
#define SMEM_B_PH   0
#define SMEM_B_PL   (128 * PKA * 2)
#define SMEM_B_VH   (2 * 128 * PKA * 2)
#define SMEM_B_VL   (SMEM_B_VH + 64 * PKA * 2)
#define SMEM_B_INV  (SMEM_B_VL + 64 * PKA * 2)
#define SMEM_B_BYTES (SMEM_B_INV + 128 * 4)

__global__ __launch_bounds__(256)
void pv_fused(float* __restrict__ attn) {
    const int it = blockIdx.x, bh = blockIdx.y;
    const int b = bh >> 4, h = bh & 15;
    const int i0 = it * 128;
    const int tid = threadIdx.x;
    float* arow = attn + (size_t)bh * TT * TT;

    extern __shared__ __align__(16) char smem[];
    __nv_bfloat16* sPh = (__nv_bfloat16*)(smem + SMEM_B_PH);
    __nv_bfloat16* sPl = (__nv_bfloat16*)(smem + SMEM_B_PL);
    __nv_bfloat16* sVh = (__nv_bfloat16*)(smem + SMEM_B_VH);
    __nv_bfloat16* sVl = (__nv_bfloat16*)(smem + SMEM_B_VL);
    float* sInv = (float*)(smem + SMEM_B_INV);

    if (tid < 128) {
        float s = 0.f;
        size_t base = ((size_t)bh * TT + i0 + tid) * NJT;
        for (int q = 0; q <= it; q++) s += g_psum[base + q];
        sInv[tid] = 1.f / s;
    }
    __syncthreads();

    const int warp = tid >> 5, lane = tid & 31;
    const int wm = warp >> 1, wn = warp & 1;
    const int grp = lane >> 2, tig = lane & 3;
    const int lm  = lane >> 3;
    const int lr  = lane & 7;
    const int a_roff = (lm & 1) * 8 + lr;
    const int a_koff = (lm >> 1) * 8;
    const int b_noff = (lm >> 1) * 8 + lr;
    const int b_koff = (lm & 1) * 8;

    float acc[2][4][4];
#pragma unroll
    for (int a = 0; a < 2; a++)
#pragma unroll
        for (int c = 0; c < 4; c++)
#pragma unroll
            for (int d = 0; d < 4; d++) acc[a][c][d] = 0.f;

    for (int jt = 0; jt <= it; jt++) {
#pragma unroll 1
        for (int jc = 0; jc < 2; jc++) {
            const int j0 = jt * 128 + jc * 64;
#pragma unroll
            for (int i = 0; i < 8; i++) {
                int idx = tid + i * 256;
                int row = idx >> 4;
                int c4  = (idx & 15) << 2;
                float inv = sInv[row];
                float4 v = *(float4*)&arow[(size_t)(i0 + row) * TT + j0 + c4];
                v.x *= inv; v.y *= inv; v.z *= inv; v.w *= inv;
                *(float4*)&arow[(size_t)(i0 + row) * TT + j0 + c4] = v;
                uint2 hp, lp;
                hilo4(v, hp, lp);
                *(uint2*)&sPh[row * PKA + c4] = hp;
                *(uint2*)&sPl[row * PKA + c4] = lp;
            }
#pragma unroll
            for (int i = 0; i < 2; i++) {
                int idx = tid + i * 256;
                int j   = idx >> 3;
                int dch = (idx & 7) << 3;
                size_t gv = ((size_t)bh * TT + j0 + j) * DD + dch;
                uint4 hv = *(const uint4*)&g_vh[gv];
                uint4 lv = *(const uint4*)&g_vl[gv];
                const __nv_bfloat16* hp = (const __nv_bfloat16*)&hv;
                const __nv_bfloat16* lp = (const __nv_bfloat16*)&lv;
#pragma unroll
                for (int e = 0; e < 8; e++) {
                    sVh[(dch + e) * PKA + j] = hp[e];
                    sVl[(dch + e) * PKA + j] = lp[e];
                }
            }
            __syncthreads();
#pragma unroll
            for (int kk = 0; kk < 64; kk += 16) {
                uint32_t bhf[4][2], blf[4][2];
#pragma unroll
                for (int p = 0; p < 2; p++) {
                    int ncol = wn * 32 + p * 16 + b_noff;
                    ldsm4(bhf[2*p][0], bhf[2*p][1], bhf[2*p+1][0], bhf[2*p+1][1],
                          &sVh[ncol * PKA + kk + b_koff]);
                    ldsm4(blf[2*p][0], blf[2*p][1], blf[2*p+1][0], blf[2*p+1][1],
                          &sVl[ncol * PKA + kk + b_koff]);
                }
#pragma unroll
                for (int mt = 0; mt < 2; mt++) {
                    int row = wm * 32 + mt * 16 + a_roff;
                    uint32_t ah[4], al[4];
                    ldsm4(ah[0], ah[1], ah[2], ah[3], &sPh[row * PKA + kk + a_koff]);
                    ldsm4(al[0], al[1], al[2], al[3], &sPl[row * PKA + kk + a_koff]);
#pragma unroll
                    for (int nt = 0; nt < 4; nt++) {
                        mma_bf16(acc[mt][nt], ah, bhf[nt]);
                        mma_bf16(acc[mt][nt], ah, blf[nt]);
                        mma_bf16(acc[mt][nt], al, bhf[nt]);
                    }
                }
            }
            __syncthreads();
        }
    }

#pragma unroll
    for (int mt = 0; mt < 2; mt++) {
#pragma unroll
        for (int nt = 0; nt < 4; nt++) {
            int t = i0 + wm * 32 + mt * 16 + grp;
            int d = wn * 32 + nt * 8 + tig * 2;
            size_t o0 = ((size_t)b * TT + t) * NE + h * DD + d;
            size_t o1 = ((size_t)b * TT + t + 8) * NE + h * DD + d;
            uint32_t ph, pl;
            pack_hl(acc[mt][nt][0], acc[mt][nt][1], ph, pl);
            *(uint32_t*)&g_avh[o0] = ph;
            *(uint32_t*)&g_avl[o0] = pl;
            pack_hl(acc[mt][nt][2], acc[mt][nt][3], ph, pl);
            *(uint32_t*)&g_avh[o1] = ph;
            *(uint32_t*)&g_avl[o1] = pl;
        }
    }
}

// ---------------------------------------------------------------------------
extern "C" void kernel_launch(void* const* d_in, const int* in_sizes, int n_in,
                              void* d_out, int out_size) {
    const float* x     = (const float*)d_in[0];
    const float* w_qkv = (const float*)d_in[1];
    const float* b_qkv = (const float*)d_in[2];
    const float* w_o   = (const float*)d_in[3];
    const float* b_o   = (const float*)d_in[4];

    float* o_out = (float*)d_out;
    float* attn;
    if ((size_t)out_size >= OSZ + ASZ) {
        attn = (float*)d_out + OSZ;
    } else {
        float* fb = nullptr;
        cudaGetSymbolAddress((void**)&fb, g_attn_fb);
        attn = fb;
    }

    __nv_bfloat16 *xh, *xl, *wqh, *wql, *woh, *wol, *avh, *avl;
    cudaGetSymbolAddress((void**)&xh,  g_xh);
    cudaGetSymbolAddress((void**)&xl,  g_xl);
    cudaGetSymbolAddress((void**)&wqh, g_wqh);
    cudaGetSymbolAddress((void**)&wql, g_wql);
    cudaGetSymbolAddress((void**)&woh, g_woh);
    cudaGetSymbolAddress((void**)&wol, g_wol);
    cudaGetSymbolAddress((void**)&avh, g_avh);
    cudaGetSymbolAddress((void**)&avl, g_avl);

    cudaFuncSetAttribute(gemm_mma<0>, cudaFuncAttributeMaxDynamicSharedMemorySize, GEMM_SMEM);
    cudaFuncSetAttribute(gemm_mma<1>, cudaFuncAttributeMaxDynamicSharedMemorySize, GEMM_SMEM);
    cudaFuncSetAttribute(scores_exp, cudaFuncAttributeMaxDynamicSharedMemorySize, SMEM_A_BYTES);
    cudaFuncSetAttribute(pv_fused,   cudaFuncAttributeMaxDynamicSharedMemorySize, SMEM_B_BYTES);

    // 0) pre-convert operands to bf16 hi/lo
    cvt_kernel<<<(BT * NE / 4 + 255) / 256, 256>>>(x, xh, xl, BT * NE / 4);
    {
        dim3 grid(N3 / 32, NE / 32);
        cvt_t_kernel<<<grid, dim3(32, 8)>>>(w_qkv, wqh, wql, NE, N3);
    }
    {
        dim3 grid(NE / 32, NE / 32);
        cvt_t_kernel<<<grid, dim3(32, 8)>>>(w_o, woh, wol, NE, NE);
    }

    // 1) QKV projection -> q/k/v bf16 hi/lo
    {
        dim3 grid(N3 / BNT, BT / BMT);
        gemm_mma<0><<<grid, 256, GEMM_SMEM>>>(xh, xl, wqh, wql, b_qkv, nullptr, NE);
    }
    // 2) scores + exp + partial row sums
    {
        dim3 grid(NJT, NJT, BH);
        scores_exp<<<grid, 256, SMEM_A_BYTES>>>(attn);
    }
    // 3) normalize (write P) + P@V -> avh/avl
    {
        dim3 grid(NJT, BH);
        pv_fused<<<grid, 256, SMEM_B_BYTES>>>(attn);
    }
    // 4) output projection
    {
        dim3 grid(NE / BNT, BT / BMT);
        gemm_mma<1><<<grid, 256, GEMM_SMEM>>>(avh, avl, woh, wol, b_o, o_out, NE);
    }
}